// round 6
// baseline (speedup 1.0000x reference)
#include <cuda_runtime.h>
#include <cuda_bf16.h>
#include <cstdint>

#define LATD 256
#define MT 64
#define NJOINT 43
#define BT 6272
#define XDIM 79

// smem layout (bytes)
#define SMEM_A_HI 0         // [64 rows][512B] swizzled bf16 H hi = 32768
#define SMEM_A_LO 32768     // H lo
#define SMEM_B    65536     // 3-stage ring x 16384 (hi 8K + lo 8K each)
#define SMEM_TOTAL (65536 + 3 * 16384)   // 114688 = 112 KB -> 2 CTAs/SM

// pre-split, pre-swizzled W2 (bf16 hi/lo), exact smem image:
// g_B[(j*16 + chunk)*16384]: bytes 0..8191 = hi (16 k-rows x 512B), 8192.. = lo
__device__ unsigned char g_B[(size_t)NJOINT * 16 * 16384];

// ---------------- helpers ----------------
__device__ __forceinline__ uint32_t smem_u32(const void* p) {
    uint32_t a;
    asm("{ .reg .u64 t; cvta.to.shared.u64 t, %1; cvt.u32.u64 %0, t; }" : "=r"(a) : "l"(p));
    return a;
}
__device__ __forceinline__ void ldsm4(uint32_t* r, uint32_t addr) {
    asm volatile("ldmatrix.sync.aligned.m8n8.x4.shared.b16 {%0,%1,%2,%3}, [%4];"
        : "=r"(r[0]), "=r"(r[1]), "=r"(r[2]), "=r"(r[3]) : "r"(addr));
}
__device__ __forceinline__ void ldsm4t(uint32_t* r, uint32_t addr) {
    asm volatile("ldmatrix.sync.aligned.m8n8.x4.trans.shared.b16 {%0,%1,%2,%3}, [%4];"
        : "=r"(r[0]), "=r"(r[1]), "=r"(r[2]), "=r"(r[3]) : "r"(addr));
}
__device__ __forceinline__ void mma_bf16(float* d, const uint32_t* a, const uint32_t* b) {
    asm volatile("mma.sync.aligned.m16n8k16.row.col.f32.bf16.bf16.f32 "
        "{%0,%1,%2,%3}, {%4,%5,%6,%7}, {%8,%9}, {%0,%1,%2,%3};"
        : "+f"(d[0]), "+f"(d[1]), "+f"(d[2]), "+f"(d[3])
        : "r"(a[0]), "r"(a[1]), "r"(a[2]), "r"(a[3]), "r"(b[0]), "r"(b[1]));
}
__device__ __forceinline__ void cp16(uint32_t dst, const void* src) {
    asm volatile("cp.async.cg.shared.global [%0], [%1], 16;" :: "r"(dst), "l"(src) : "memory");
}
#define CP_COMMIT() asm volatile("cp.async.commit_group;" ::: "memory")
#define CP_WAIT(n)  asm volatile("cp.async.wait_group %0;" :: "n"(n) : "memory")

__device__ __forceinline__ void split_bf16(float v, unsigned short& hi, unsigned short& lo) {
    __nv_bfloat16 h = __float2bfloat16(v);
    hi = __bfloat16_as_ushort(h);
    lo = __bfloat16_as_ushort(__float2bfloat16(v - __bfloat162float(h)));
}

// ---------------- W2 pre-split prologue ----------------
__global__ void __launch_bounds__(256)
w2_split_kernel(const float* __restrict__ W2_3, const float* __restrict__ W2_2,
                const float* __restrict__ W2_1)
{
    const int blk = blockIdx.x;
    const int j = blk >> 4, c = blk & 15;
    const float* W2;
    if (j < 13)      W2 = W2_3 + (size_t)j * LATD * LATD;
    else if (j < 23) W2 = W2_2 + (size_t)(j - 13) * LATD * LATD;
    else             W2 = W2_1 + (size_t)(j - 23) * LATD * LATD;

    unsigned char* dst = g_B + (size_t)blk * 16384;
    const int t = threadIdx.x;
    #pragma unroll
    for (int q = 0; q < 2; ++q) {
        int pid = t + q * 256;       // 0..511
        int kr = pid >> 5;           // 0..15 (k within chunk)
        int nb = pid & 31;           // 0..31 (8-col block)
        const float* src = W2 + (size_t)(c * 16 + kr) * LATD + nb * 8;
        float4 v0 = *(const float4*)src;
        float4 v1 = *(const float4*)(src + 4);
        unsigned short h[8], l[8];
        split_bf16(v0.x, h[0], l[0]); split_bf16(v0.y, h[1], l[1]);
        split_bf16(v0.z, h[2], l[2]); split_bf16(v0.w, h[3], l[3]);
        split_bf16(v1.x, h[4], l[4]); split_bf16(v1.y, h[5], l[5]);
        split_bf16(v1.z, h[6], l[6]); split_bf16(v1.w, h[7], l[7]);
        uint4 ph, pl;
        ph.x = h[0] | ((uint32_t)h[1] << 16); ph.y = h[2] | ((uint32_t)h[3] << 16);
        ph.z = h[4] | ((uint32_t)h[5] << 16); ph.w = h[6] | ((uint32_t)h[7] << 16);
        pl.x = l[0] | ((uint32_t)l[1] << 16); pl.y = l[2] | ((uint32_t)l[3] << 16);
        pl.z = l[4] | ((uint32_t)l[5] << 16); pl.w = l[6] | ((uint32_t)l[7] << 16);
        uint32_t off = (uint32_t)(kr * 512) + (uint32_t)((nb ^ (kr & 7)) << 4);
        *(uint4*)(dst + off)        = ph;
        *(uint4*)(dst + 8192 + off) = pl;
    }
}

// ---------------- main kernel ----------------
__global__ void __launch_bounds__(256, 2)
me_hmma_kernel(const float* __restrict__ x,
               const float* __restrict__ W1_3, const float* __restrict__ b1_3,
               const float* __restrict__ b2_3,
               const float* __restrict__ W1_2, const float* __restrict__ b1_2,
               const float* __restrict__ b2_2,
               const float* __restrict__ W1_1, const float* __restrict__ b1_1,
               const float* __restrict__ b2_1,
               float* __restrict__ out)
{
    extern __shared__ char smem[];
    const uint32_t sb  = smem_u32(smem);
    const uint32_t sbB = sb + SMEM_B;
    const int t = threadIdx.x;
    const int lane = t & 31, wid = t >> 5;
    const int j = blockIdx.y;
    const int m0 = blockIdx.x * MT;

    // per-joint meta
    int d, xoff;
    const float *W1, *b1, *b2;
    if (j < 13)      { d = 3; xoff = j * 3;
        W1 = W1_3 + j * 3 * LATD; b1 = b1_3 + j * LATD; b2 = b2_3 + j * LATD; }
    else if (j < 23) { int jj = j - 13; d = 2; xoff = 39 + jj * 2;
        W1 = W1_2 + jj * 2 * LATD; b1 = b1_2 + jj * LATD; b2 = b2_2 + jj * LATD; }
    else             { int jj = j - 23; d = 1; xoff = 59 + jj;
        W1 = W1_1 + jj * LATD;     b1 = b1_1 + jj * LATD; b2 = b2_1 + jj * LATD; }

    const unsigned char* gB = g_B + (size_t)j * 16 * 16384;
    const unsigned char* gBt = gB + t * 16;     // per-thread base for prefetch

    // ---- prefetch B chunks 0,1 into stages 0,1 (overlaps phase 1) ----
    {
        uint32_t dst0 = sbB + t * 16;
        #pragma unroll
        for (int q = 0; q < 4; ++q) cp16(dst0 + q * 4096, gBt + q * 4096);
        CP_COMMIT();
        uint32_t dst1 = sbB + 16384 + t * 16;
        #pragma unroll
        for (int q = 0; q < 4; ++q) cp16(dst1 + q * 4096, gBt + 16384 + q * 4096);
        CP_COMMIT();
    }

    // ---- phase 1: H = gelu_tanh(x*W1 + b1) -> swizzled bf16 hi/lo A tiles ----
    {
        const int kbase = lane * 8;
        float w1r[3][8], b1r[8];
        #pragma unroll
        for (int e = 0; e < 8; ++e) b1r[e] = b1[kbase + e];
        #pragma unroll
        for (int i = 0; i < 3; ++i)
            #pragma unroll
            for (int e = 0; e < 8; ++e)
                w1r[i][e] = (i < d) ? W1[i * LATD + kbase + e] : 0.0f;

        #pragma unroll 2
        for (int it = 0; it < 8; ++it) {
            const int m = wid + it * 8;
            const float* xp = x + (size_t)(m0 + m) * XDIM + xoff;
            float x0 = xp[0];
            float x1 = (d > 1) ? xp[1] : 0.0f;
            float x2 = (d > 2) ? xp[2] : 0.0f;
            uint32_t ph[4], pl[4];
            #pragma unroll
            for (int e2 = 0; e2 < 4; ++e2) {
                unsigned short hh[2], ll[2];
                #pragma unroll
                for (int e = 0; e < 2; ++e) {
                    const int e8 = e2 * 2 + e;
                    float h = b1r[e8] + x0 * w1r[0][e8] + x1 * w1r[1][e8] + x2 * w1r[2][e8];
                    float cc = 0.7978845608028654f * fmaf(0.044715f * h, h * h, h);
                    float u = 2.8853900817779268f * cc;       // 2c * log2(e)
                    float te; asm("ex2.approx.f32 %0, %1;" : "=f"(te) : "f"(u));
                    float rc; asm("rcp.approx.f32 %0, %1;" : "=f"(rc) : "f"(te + 1.0f));
                    float g = fmaf(-h, rc, h);                // gelu_tanh(h)
                    split_bf16(g, hh[e], ll[e]);
                }
                ph[e2] = hh[0] | ((uint32_t)hh[1] << 16);
                pl[e2] = ll[0] | ((uint32_t)ll[1] << 16);
            }
            uint32_t addr = (uint32_t)(m * 512) + (uint32_t)((lane ^ (m & 7)) << 4);
            *(uint4*)(smem + SMEM_A_HI + addr) = make_uint4(ph[0], ph[1], ph[2], ph[3]);
            *(uint4*)(smem + SMEM_A_LO + addr) = make_uint4(pl[0], pl[1], pl[2], pl[3]);
        }
    }

    // ---- phase 2: split-bf16 HMMA, warp tile 32x64, 3-stage ring, 1 sync/chunk ----
    const int wm = wid >> 2, wn = wid & 3;
    const int M0 = wm * 32, N0 = wn * 64;
    const uint32_t s = lane & 7;
    const uint32_t ktop = lane >> 4;                       // 0/1
    const uint32_t rA = (uint32_t)M0 + ((lane >> 3) & 1) * 8 + s;
    uint32_t aBase[2];
    #pragma unroll
    for (int mf = 0; mf < 2; ++mf) aBase[mf] = sb + (rA + mf * 16) * 512;
    const uint32_t krb = ((lane >> 3) & 1) * 8 + s;        // k row within chunk
    uint32_t cBoff[4];
    #pragma unroll
    for (int nfp = 0; nfp < 4; ++nfp)
        cBoff[nfp] = (((uint32_t)(N0 / 8 + nfp * 2) + ktop) ^ s) << 4;

    // hoist b2 loads off the epilogue critical path
    const int colb = 2 * (lane & 3);
    float2 b2v[8];
    #pragma unroll
    for (int nf = 0; nf < 8; ++nf)
        b2v[nf] = *(const float2*)(b2 + N0 + nf * 8 + colb);

    float acc[2][8][4];
    #pragma unroll
    for (int mf = 0; mf < 2; ++mf)
        #pragma unroll
        for (int nf = 0; nf < 8; ++nf)
            #pragma unroll
            for (int e = 0; e < 4; ++e) acc[mf][nf][e] = 0.0f;

    // ring stage registers: cur = chunk c, nxt = c+1, prv = freed (gets c+2)
    uint32_t bufCur = sbB, bufNxt = sbB + 16384, bufPrv = sbB + 32768;
    const uint32_t tOff = (uint32_t)t * 16;

    #pragma unroll 1
    for (int c = 0; c < 16; ++c) {
        if (c < 14) { CP_WAIT(1); } else { CP_WAIT(0); }
        __syncthreads();          // chunk c visible to all; all warps done with c-1

        // earliest-legal prefetch: chunk c+2 into the stage chunk c-1 occupied
        if (c + 2 < 16) {
            uint32_t dst = bufPrv + tOff;
            const unsigned char* sp = gBt + (size_t)(c + 2) * 16384;
            #pragma unroll
            for (int q = 0; q < 4; ++q) cp16(dst + q * 4096, sp + q * 4096);
            CP_COMMIT();
        }

        // compute chunk c from bufCur
        uint32_t ah[2][4], al[2][4];
        const uint32_t koffA = (((uint32_t)(c * 2) + ktop) ^ s) << 4;
        #pragma unroll
        for (int mf = 0; mf < 2; ++mf) {
            ldsm4(ah[mf], aBase[mf] + koffA);
            ldsm4(al[mf], aBase[mf] + 32768 + koffA);
        }
        const uint32_t rowB = bufCur + krb * 512;
        #pragma unroll
        for (int nfp = 0; nfp < 4; ++nfp) {
            uint32_t bh[2][2], bl[2][2];
            ldsm4t(&bh[0][0], rowB + cBoff[nfp]);
            ldsm4t(&bl[0][0], rowB + 8192 + cBoff[nfp]);
            #pragma unroll
            for (int mf = 0; mf < 2; ++mf)
                #pragma unroll
                for (int nn = 0; nn < 2; ++nn) {
                    float* a4 = acc[mf][nfp * 2 + nn];
                    mma_bf16(a4, ah[mf], bh[nn]);
                    mma_bf16(a4, ah[mf], bl[nn]);
                    mma_bf16(a4, al[mf], bh[nn]);
                }
        }

        // rotate ring
        uint32_t tmp = bufCur;
        bufCur = bufNxt; bufNxt = bufPrv; bufPrv = tmp;
    }

    // ---- epilogue: + b2, write out [BT, 43, 256] ----
    {
        #pragma unroll
        for (int mf = 0; mf < 2; ++mf) {
            const int row = M0 + mf * 16 + (lane >> 2);
            float* p0 = out + ((size_t)(m0 + row) * NJOINT + j) * LATD;
            float* p1 = p0 + (size_t)8 * NJOINT * LATD;
            #pragma unroll
            for (int nf = 0; nf < 8; ++nf) {
                const int col = N0 + nf * 8 + colb;
                float2 v0, v1;
                v0.x = acc[mf][nf][0] + b2v[nf].x;
                v0.y = acc[mf][nf][1] + b2v[nf].y;
                v1.x = acc[mf][nf][2] + b2v[nf].x;
                v1.y = acc[mf][nf][3] + b2v[nf].y;
                *(float2*)(p0 + col) = v0;
                *(float2*)(p1 + col) = v1;
            }
        }
    }
}

extern "C" void kernel_launch(void* const* d_in, const int* in_sizes, int n_in,
                              void* d_out, int out_size)
{
    (void)in_sizes; (void)n_in; (void)out_size;
    cudaFuncSetAttribute(me_hmma_kernel,
                         cudaFuncAttributeMaxDynamicSharedMemorySize, SMEM_TOTAL);

    const float* x    = (const float*)d_in[0];
    const float* W1_3 = (const float*)d_in[1];
    const float* b1_3 = (const float*)d_in[2];
    const float* W2_3 = (const float*)d_in[3];
    const float* b2_3 = (const float*)d_in[4];
    const float* W1_2 = (const float*)d_in[5];
    const float* b1_2 = (const float*)d_in[6];
    const float* W2_2 = (const float*)d_in[7];
    const float* b2_2 = (const float*)d_in[8];
    const float* W1_1 = (const float*)d_in[9];
    const float* b1_1 = (const float*)d_in[10];
    const float* W2_1 = (const float*)d_in[11];
    const float* b2_1 = (const float*)d_in[12];

    w2_split_kernel<<<NJOINT * 16, 256>>>(W2_3, W2_2, W2_1);

    dim3 grid(BT / MT, NJOINT);   // 98 x 43
    me_hmma_kernel<<<grid, 256, SMEM_TOTAL>>>(
        x, W1_3, b1_3, b2_3,
        W1_2, b1_2, b2_2,
        W1_1, b1_1, b2_1,
        (float*)d_out);
}

// round 7
// speedup vs baseline: 1.2378x; 1.2378x over previous
#include <cuda_runtime.h>
#include <cuda_fp16.h>
#include <cstdint>

#define LATD 256
#define MT 64
#define NJOINT 43
#define BT 6272
#define XDIM 79

// smem layout (bytes)
#define SMEM_A    0         // [64 rows][512B] swizzled fp16 H = 32768
#define SMEM_B    32768     // 3-stage ring x 16384 (hi 8K + lo 8K each)
#define SMEM_TOTAL (32768 + 3 * 16384)   // 81920 -> 2 CTAs/SM easily

// pre-split, pre-swizzled W2 (fp16 hi/lo), exact smem image:
// g_B[(j*16 + chunk)*16384]: bytes 0..8191 = hi (16 k-rows x 512B), 8192.. = lo
__device__ unsigned char g_B[(size_t)NJOINT * 16 * 16384];

// ---------------- helpers ----------------
__device__ __forceinline__ uint32_t smem_u32(const void* p) {
    uint32_t a;
    asm("{ .reg .u64 t; cvta.to.shared.u64 t, %1; cvt.u32.u64 %0, t; }" : "=r"(a) : "l"(p));
    return a;
}
__device__ __forceinline__ void ldsm4(uint32_t* r, uint32_t addr) {
    asm volatile("ldmatrix.sync.aligned.m8n8.x4.shared.b16 {%0,%1,%2,%3}, [%4];"
        : "=r"(r[0]), "=r"(r[1]), "=r"(r[2]), "=r"(r[3]) : "r"(addr));
}
__device__ __forceinline__ void ldsm4t(uint32_t* r, uint32_t addr) {
    asm volatile("ldmatrix.sync.aligned.m8n8.x4.trans.shared.b16 {%0,%1,%2,%3}, [%4];"
        : "=r"(r[0]), "=r"(r[1]), "=r"(r[2]), "=r"(r[3]) : "r"(addr));
}
__device__ __forceinline__ void mma_f16(float* d, const uint32_t* a, const uint32_t* b) {
    asm volatile("mma.sync.aligned.m16n8k16.row.col.f32.f16.f16.f32 "
        "{%0,%1,%2,%3}, {%4,%5,%6,%7}, {%8,%9}, {%0,%1,%2,%3};"
        : "+f"(d[0]), "+f"(d[1]), "+f"(d[2]), "+f"(d[3])
        : "r"(a[0]), "r"(a[1]), "r"(a[2]), "r"(a[3]), "r"(b[0]), "r"(b[1]));
}
__device__ __forceinline__ void cp16(uint32_t dst, const void* src) {
    asm volatile("cp.async.cg.shared.global [%0], [%1], 16;" :: "r"(dst), "l"(src) : "memory");
}
#define CP_COMMIT() asm volatile("cp.async.commit_group;" ::: "memory")
#define CP_WAIT(n)  asm volatile("cp.async.wait_group %0;" :: "n"(n) : "memory")

__device__ __forceinline__ void split_f16(float v, unsigned short& hi, unsigned short& lo) {
    __half h = __float2half_rn(v);
    hi = __half_as_ushort(h);
    lo = __half_as_ushort(__float2half_rn(v - __half2float(h)));
}

// ---------------- W2 pre-split prologue (fp16 hi/lo) ----------------
__global__ void __launch_bounds__(256)
w2_split_kernel(const float* __restrict__ W2_3, const float* __restrict__ W2_2,
                const float* __restrict__ W2_1)
{
    const int blk = blockIdx.x;
    const int j = blk >> 4, c = blk & 15;
    const float* W2;
    if (j < 13)      W2 = W2_3 + (size_t)j * LATD * LATD;
    else if (j < 23) W2 = W2_2 + (size_t)(j - 13) * LATD * LATD;
    else             W2 = W2_1 + (size_t)(j - 23) * LATD * LATD;

    unsigned char* dst = g_B + (size_t)blk * 16384;
    const int t = threadIdx.x;
    #pragma unroll
    for (int q = 0; q < 2; ++q) {
        int pid = t + q * 256;       // 0..511
        int kr = pid >> 5;           // 0..15 (k within chunk)
        int nb = pid & 31;           // 0..31 (8-col block)
        const float* src = W2 + (size_t)(c * 16 + kr) * LATD + nb * 8;
        float4 v0 = *(const float4*)src;
        float4 v1 = *(const float4*)(src + 4);
        unsigned short h[8], l[8];
        split_f16(v0.x, h[0], l[0]); split_f16(v0.y, h[1], l[1]);
        split_f16(v0.z, h[2], l[2]); split_f16(v0.w, h[3], l[3]);
        split_f16(v1.x, h[4], l[4]); split_f16(v1.y, h[5], l[5]);
        split_f16(v1.z, h[6], l[6]); split_f16(v1.w, h[7], l[7]);
        uint4 ph, pl;
        ph.x = h[0] | ((uint32_t)h[1] << 16); ph.y = h[2] | ((uint32_t)h[3] << 16);
        ph.z = h[4] | ((uint32_t)h[5] << 16); ph.w = h[6] | ((uint32_t)h[7] << 16);
        pl.x = l[0] | ((uint32_t)l[1] << 16); pl.y = l[2] | ((uint32_t)l[3] << 16);
        pl.z = l[4] | ((uint32_t)l[5] << 16); pl.w = l[6] | ((uint32_t)l[7] << 16);
        uint32_t off = (uint32_t)(kr * 512) + (uint32_t)((nb ^ (kr & 7)) << 4);
        *(uint4*)(dst + off)        = ph;
        *(uint4*)(dst + 8192 + off) = pl;
    }
}

// ---------------- main kernel ----------------
__global__ void __launch_bounds__(256, 2)
me_hmma_kernel(const float* __restrict__ x,
               const float* __restrict__ W1_3, const float* __restrict__ b1_3,
               const float* __restrict__ b2_3,
               const float* __restrict__ W1_2, const float* __restrict__ b1_2,
               const float* __restrict__ b2_2,
               const float* __restrict__ W1_1, const float* __restrict__ b1_1,
               const float* __restrict__ b2_1,
               float* __restrict__ out)
{
    extern __shared__ char smem[];
    const uint32_t sb  = smem_u32(smem);
    const uint32_t sbB = sb + SMEM_B;
    const int t = threadIdx.x;
    const int lane = t & 31, wid = t >> 5;
    const int j = blockIdx.y;
    const int m0 = blockIdx.x * MT;

    // per-joint meta
    int d, xoff;
    const float *W1, *b1, *b2;
    if (j < 13)      { d = 3; xoff = j * 3;
        W1 = W1_3 + j * 3 * LATD; b1 = b1_3 + j * LATD; b2 = b2_3 + j * LATD; }
    else if (j < 23) { int jj = j - 13; d = 2; xoff = 39 + jj * 2;
        W1 = W1_2 + jj * 2 * LATD; b1 = b1_2 + jj * LATD; b2 = b2_2 + jj * LATD; }
    else             { int jj = j - 23; d = 1; xoff = 59 + jj;
        W1 = W1_1 + jj * LATD;     b1 = b1_1 + jj * LATD; b2 = b2_1 + jj * LATD; }

    const unsigned char* gB = g_B + (size_t)j * 16 * 16384;
    const unsigned char* gBt = gB + t * 16;     // per-thread base for prefetch

    // ---- prefetch B chunks 0,1 into stages 0,1 (overlaps phase 1) ----
    {
        uint32_t dst0 = sbB + t * 16;
        #pragma unroll
        for (int q = 0; q < 4; ++q) cp16(dst0 + q * 4096, gBt + q * 4096);
        CP_COMMIT();
        uint32_t dst1 = sbB + 16384 + t * 16;
        #pragma unroll
        for (int q = 0; q < 4; ++q) cp16(dst1 + q * 4096, gBt + 16384 + q * 4096);
        CP_COMMIT();
    }

    // ---- phase 1: H = gelu_tanh(x*W1 + b1) -> swizzled fp16 A tile ----
    {
        const int kbase = lane * 8;
        float w1r[3][8], b1r[8];
        #pragma unroll
        for (int e = 0; e < 8; ++e) b1r[e] = b1[kbase + e];
        #pragma unroll
        for (int i = 0; i < 3; ++i)
            #pragma unroll
            for (int e = 0; e < 8; ++e)
                w1r[i][e] = (i < d) ? W1[i * LATD + kbase + e] : 0.0f;

        #pragma unroll 2
        for (int it = 0; it < 8; ++it) {
            const int m = wid + it * 8;
            const float* xp = x + (size_t)(m0 + m) * XDIM + xoff;
            float x0 = xp[0];
            float x1 = (d > 1) ? xp[1] : 0.0f;
            float x2 = (d > 2) ? xp[2] : 0.0f;
            uint32_t ph[4];
            #pragma unroll
            for (int e2 = 0; e2 < 4; ++e2) {
                unsigned short hh[2];
                #pragma unroll
                for (int e = 0; e < 2; ++e) {
                    const int e8 = e2 * 2 + e;
                    float h = b1r[e8] + x0 * w1r[0][e8] + x1 * w1r[1][e8] + x2 * w1r[2][e8];
                    float cc = 0.7978845608028654f * fmaf(0.044715f * h, h * h, h);
                    float u = 2.8853900817779268f * cc;       // 2c * log2(e)
                    float te; asm("ex2.approx.f32 %0, %1;" : "=f"(te) : "f"(u));
                    float rc; asm("rcp.approx.f32 %0, %1;" : "=f"(rc) : "f"(te + 1.0f));
                    float g = fmaf(-h, rc, h);                // gelu_tanh(h)
                    hh[e] = __half_as_ushort(__float2half_rn(g));
                }
                ph[e2] = hh[0] | ((uint32_t)hh[1] << 16);
            }
            uint32_t addr = (uint32_t)(m * 512) + (uint32_t)((lane ^ (m & 7)) << 4);
            *(uint4*)(smem + SMEM_A + addr) = make_uint4(ph[0], ph[1], ph[2], ph[3]);
        }
    }

    // ---- phase 2: 2-pass fp16 HMMA, warp tile 32x64, 3-stage ring ----
    const int wm = wid >> 2, wn = wid & 3;
    const int M0 = wm * 32, N0 = wn * 64;
    const uint32_t s = lane & 7;
    const uint32_t ktop = lane >> 4;                       // 0/1
    const uint32_t rA = (uint32_t)M0 + ((lane >> 3) & 1) * 8 + s;
    uint32_t aBase[2];
    #pragma unroll
    for (int mf = 0; mf < 2; ++mf) aBase[mf] = sb + (rA + mf * 16) * 512;
    const uint32_t krb = ((lane >> 3) & 1) * 8 + s;        // k row within chunk
    uint32_t cBoff[4];
    #pragma unroll
    for (int nfp = 0; nfp < 4; ++nfp)
        cBoff[nfp] = (((uint32_t)(N0 / 8 + nfp * 2) + ktop) ^ s) << 4;

    // hoist b2 loads off the epilogue critical path
    const int colb = 2 * (lane & 3);
    float2 b2v[8];
    #pragma unroll
    for (int nf = 0; nf < 8; ++nf)
        b2v[nf] = *(const float2*)(b2 + N0 + nf * 8 + colb);

    float acc[2][8][4];
    #pragma unroll
    for (int mf = 0; mf < 2; ++mf)
        #pragma unroll
        for (int nf = 0; nf < 8; ++nf)
            #pragma unroll
            for (int e = 0; e < 4; ++e) acc[mf][nf][e] = 0.0f;

    // ring stage registers: cur = chunk c, nxt = c+1, prv = freed (gets c+2)
    uint32_t bufCur = sbB, bufNxt = sbB + 16384, bufPrv = sbB + 32768;
    const uint32_t tOff = (uint32_t)t * 16;

    #pragma unroll 1
    for (int c = 0; c < 16; ++c) {
        if (c < 14) { CP_WAIT(1); } else { CP_WAIT(0); }
        __syncthreads();          // chunk c visible; all warps done with c-1

        // prefetch chunk c+2 into the stage chunk c-1 occupied
        if (c + 2 < 16) {
            uint32_t dst = bufPrv + tOff;
            const unsigned char* sp = gBt + (size_t)(c + 2) * 16384;
            #pragma unroll
            for (int q = 0; q < 4; ++q) cp16(dst + q * 4096, sp + q * 4096);
            CP_COMMIT();
        }

        // compute chunk c from bufCur
        uint32_t ah[2][4];
        const uint32_t koffA = (((uint32_t)(c * 2) + ktop) ^ s) << 4;
        #pragma unroll
        for (int mf = 0; mf < 2; ++mf)
            ldsm4(ah[mf], aBase[mf] + koffA);

        const uint32_t rowB = bufCur + krb * 512;
        #pragma unroll
        for (int nfp = 0; nfp < 4; ++nfp) {
            uint32_t bh[2][2], bl[2][2];
            ldsm4t(&bh[0][0], rowB + cBoff[nfp]);
            ldsm4t(&bl[0][0], rowB + 8192 + cBoff[nfp]);
            #pragma unroll
            for (int mf = 0; mf < 2; ++mf)
                #pragma unroll
                for (int nn = 0; nn < 2; ++nn) {
                    float* a4 = acc[mf][nfp * 2 + nn];
                    mma_f16(a4, ah[mf], bh[nn]);
                    mma_f16(a4, ah[mf], bl[nn]);
                }
        }

        // rotate ring
        uint32_t tmp = bufCur;
        bufCur = bufNxt; bufNxt = bufPrv; bufPrv = tmp;
    }

    // ---- epilogue: + b2, write out [BT, 43, 256] ----
    {
        #pragma unroll
        for (int mf = 0; mf < 2; ++mf) {
            const int row = M0 + mf * 16 + (lane >> 2);
            float* p0 = out + ((size_t)(m0 + row) * NJOINT + j) * LATD;
            float* p1 = p0 + (size_t)8 * NJOINT * LATD;
            #pragma unroll
            for (int nf = 0; nf < 8; ++nf) {
                const int col = N0 + nf * 8 + colb;
                float2 v0, v1;
                v0.x = acc[mf][nf][0] + b2v[nf].x;
                v0.y = acc[mf][nf][1] + b2v[nf].y;
                v1.x = acc[mf][nf][2] + b2v[nf].x;
                v1.y = acc[mf][nf][3] + b2v[nf].y;
                *(float2*)(p0 + col) = v0;
                *(float2*)(p1 + col) = v1;
            }
        }
    }
}

extern "C" void kernel_launch(void* const* d_in, const int* in_sizes, int n_in,
                              void* d_out, int out_size)
{
    (void)in_sizes; (void)n_in; (void)out_size;
    cudaFuncSetAttribute(me_hmma_kernel,
                         cudaFuncAttributeMaxDynamicSharedMemorySize, SMEM_TOTAL);

    const float* x    = (const float*)d_in[0];
    const float* W1_3 = (const float*)d_in[1];
    const float* b1_3 = (const float*)d_in[2];
    const float* W2_3 = (const float*)d_in[3];
    const float* b2_3 = (const float*)d_in[4];
    const float* W1_2 = (const float*)d_in[5];
    const float* b1_2 = (const float*)d_in[6];
    const float* W2_2 = (const float*)d_in[7];
    const float* b2_2 = (const float*)d_in[8];
    const float* W1_1 = (const float*)d_in[9];
    const float* b1_1 = (const float*)d_in[10];
    const float* W2_1 = (const float*)d_in[11];
    const float* b2_1 = (const float*)d_in[12];

    w2_split_kernel<<<NJOINT * 16, 256>>>(W2_3, W2_2, W2_1);

    dim3 grid(BT / MT, NJOINT);   // 98 x 43
    me_hmma_kernel<<<grid, 256, SMEM_TOTAL>>>(
        x, W1_3, b1_3, b2_3,
        W1_2, b1_2, b2_2,
        W1_1, b1_1, b2_1,
        (float*)d_out);
}

// round 8
// speedup vs baseline: 1.7160x; 1.3863x over previous
#include <cuda_runtime.h>
#include <cuda_fp16.h>
#include <cstdint>

#define LATD 256
#define MT 64
#define NJOINT 43
#define BT 6272
#define XDIM 79

// smem layout (bytes)
#define SMEM_A    0         // [64 rows][512B] swizzled fp16 H = 32768
#define SMEM_B    32768     // 3-stage ring x 16384 (32 k-rows x 512B each)
#define SMEM_TOTAL (32768 + 3 * 16384)   // 81920 -> 2 CTAs/SM

// pre-swizzled fp16 W2, exact smem image:
// g_B[(j*8 + chunk)*16384]: 32 k-rows x 512B (256 n-cols fp16), XOR-swizzled
__device__ unsigned char g_B[(size_t)NJOINT * 8 * 16384];

// ---------------- helpers ----------------
__device__ __forceinline__ uint32_t smem_u32(const void* p) {
    uint32_t a;
    asm("{ .reg .u64 t; cvta.to.shared.u64 t, %1; cvt.u32.u64 %0, t; }" : "=r"(a) : "l"(p));
    return a;
}
__device__ __forceinline__ void ldsm4(uint32_t* r, uint32_t addr) {
    asm volatile("ldmatrix.sync.aligned.m8n8.x4.shared.b16 {%0,%1,%2,%3}, [%4];"
        : "=r"(r[0]), "=r"(r[1]), "=r"(r[2]), "=r"(r[3]) : "r"(addr));
}
__device__ __forceinline__ void ldsm4t(uint32_t* r, uint32_t addr) {
    asm volatile("ldmatrix.sync.aligned.m8n8.x4.trans.shared.b16 {%0,%1,%2,%3}, [%4];"
        : "=r"(r[0]), "=r"(r[1]), "=r"(r[2]), "=r"(r[3]) : "r"(addr));
}
__device__ __forceinline__ void mma_f16(float* d, const uint32_t* a, const uint32_t* b) {
    asm volatile("mma.sync.aligned.m16n8k16.row.col.f32.f16.f16.f32 "
        "{%0,%1,%2,%3}, {%4,%5,%6,%7}, {%8,%9}, {%0,%1,%2,%3};"
        : "+f"(d[0]), "+f"(d[1]), "+f"(d[2]), "+f"(d[3])
        : "r"(a[0]), "r"(a[1]), "r"(a[2]), "r"(a[3]), "r"(b[0]), "r"(b[1]));
}
__device__ __forceinline__ void cp16(uint32_t dst, const void* src) {
    asm volatile("cp.async.cg.shared.global [%0], [%1], 16;" :: "r"(dst), "l"(src) : "memory");
}
#define CP_COMMIT() asm volatile("cp.async.commit_group;" ::: "memory")
#define CP_WAIT(n)  asm volatile("cp.async.wait_group %0;" :: "n"(n) : "memory")

// ---------------- W2 pre-convert prologue (single fp16, swizzled) ----------------
// grid = NJOINT*8 (j*8 + chunk of 32 k-rows), 256 threads
__global__ void __launch_bounds__(256)
w2_split_kernel(const float* __restrict__ W2_3, const float* __restrict__ W2_2,
                const float* __restrict__ W2_1)
{
    const int blk = blockIdx.x;
    const int j = blk >> 3, c = blk & 7;
    const float* W2;
    if (j < 13)      W2 = W2_3 + (size_t)j * LATD * LATD;
    else if (j < 23) W2 = W2_2 + (size_t)(j - 13) * LATD * LATD;
    else             W2 = W2_1 + (size_t)(j - 23) * LATD * LATD;

    unsigned char* dst = g_B + (size_t)blk * 16384;
    const int t = threadIdx.x;
    #pragma unroll
    for (int q = 0; q < 4; ++q) {
        int pid = t + q * 256;       // 0..1023
        int kr = pid >> 5;           // 0..31 (k within chunk)
        int nb = pid & 31;           // 0..31 (8-col block)
        const float* src = W2 + (size_t)(c * 32 + kr) * LATD + nb * 8;
        float4 v0 = *(const float4*)src;
        float4 v1 = *(const float4*)(src + 4);
        unsigned short h[8];
        h[0] = __half_as_ushort(__float2half_rn(v0.x));
        h[1] = __half_as_ushort(__float2half_rn(v0.y));
        h[2] = __half_as_ushort(__float2half_rn(v0.z));
        h[3] = __half_as_ushort(__float2half_rn(v0.w));
        h[4] = __half_as_ushort(__float2half_rn(v1.x));
        h[5] = __half_as_ushort(__float2half_rn(v1.y));
        h[6] = __half_as_ushort(__float2half_rn(v1.z));
        h[7] = __half_as_ushort(__float2half_rn(v1.w));
        uint4 ph;
        ph.x = h[0] | ((uint32_t)h[1] << 16); ph.y = h[2] | ((uint32_t)h[3] << 16);
        ph.z = h[4] | ((uint32_t)h[5] << 16); ph.w = h[6] | ((uint32_t)h[7] << 16);
        uint32_t off = (uint32_t)(kr * 512) + (uint32_t)((nb ^ (kr & 7)) << 4);
        *(uint4*)(dst + off) = ph;
    }
}

// ---------------- main kernel ----------------
__global__ void __launch_bounds__(256, 2)
me_hmma_kernel(const float* __restrict__ x,
               const float* __restrict__ W1_3, const float* __restrict__ b1_3,
               const float* __restrict__ b2_3,
               const float* __restrict__ W1_2, const float* __restrict__ b1_2,
               const float* __restrict__ b2_2,
               const float* __restrict__ W1_1, const float* __restrict__ b1_1,
               const float* __restrict__ b2_1,
               float* __restrict__ out)
{
    extern __shared__ char smem[];
    const uint32_t sb  = smem_u32(smem);
    const uint32_t sbB = sb + SMEM_B;
    const int t = threadIdx.x;
    const int lane = t & 31, wid = t >> 5;
    const int j = blockIdx.y;
    const int m0 = blockIdx.x * MT;

    // per-joint meta
    int d, xoff;
    const float *W1, *b1, *b2;
    if (j < 13)      { d = 3; xoff = j * 3;
        W1 = W1_3 + j * 3 * LATD; b1 = b1_3 + j * LATD; b2 = b2_3 + j * LATD; }
    else if (j < 23) { int jj = j - 13; d = 2; xoff = 39 + jj * 2;
        W1 = W1_2 + jj * 2 * LATD; b1 = b1_2 + jj * LATD; b2 = b2_2 + jj * LATD; }
    else             { int jj = j - 23; d = 1; xoff = 59 + jj;
        W1 = W1_1 + jj * LATD;     b1 = b1_1 + jj * LATD; b2 = b2_1 + jj * LATD; }

    const unsigned char* gB = g_B + (size_t)j * 8 * 16384;
    const unsigned char* gBt = gB + t * 16;     // per-thread base for prefetch

    // ---- prefetch B chunks 0,1 into stages 0,1 (overlaps phase 1) ----
    {
        uint32_t dst0 = sbB + t * 16;
        #pragma unroll
        for (int q = 0; q < 4; ++q) cp16(dst0 + q * 4096, gBt + q * 4096);
        CP_COMMIT();
        uint32_t dst1 = sbB + 16384 + t * 16;
        #pragma unroll
        for (int q = 0; q < 4; ++q) cp16(dst1 + q * 4096, gBt + 16384 + q * 4096);
        CP_COMMIT();
    }

    // ---- phase 1: H = gelu_tanh(x*W1 + b1) -> swizzled fp16 A tile ----
    {
        const int kbase = lane * 8;
        float w1r[3][8], b1r[8];
        #pragma unroll
        for (int e = 0; e < 8; ++e) b1r[e] = b1[kbase + e];
        #pragma unroll
        for (int i = 0; i < 3; ++i)
            #pragma unroll
            for (int e = 0; e < 8; ++e)
                w1r[i][e] = (i < d) ? W1[i * LATD + kbase + e] : 0.0f;

        #pragma unroll 2
        for (int it = 0; it < 8; ++it) {
            const int m = wid + it * 8;
            const float* xp = x + (size_t)(m0 + m) * XDIM + xoff;
            float x0 = xp[0];
            float x1 = (d > 1) ? xp[1] : 0.0f;
            float x2 = (d > 2) ? xp[2] : 0.0f;
            uint32_t ph[4];
            #pragma unroll
            for (int e2 = 0; e2 < 4; ++e2) {
                unsigned short hh[2];
                #pragma unroll
                for (int e = 0; e < 2; ++e) {
                    const int e8 = e2 * 2 + e;
                    float h = b1r[e8] + x0 * w1r[0][e8] + x1 * w1r[1][e8] + x2 * w1r[2][e8];
                    float cc = 0.7978845608028654f * fmaf(0.044715f * h, h * h, h);
                    float u = 2.8853900817779268f * cc;       // 2c * log2(e)
                    float te; asm("ex2.approx.f32 %0, %1;" : "=f"(te) : "f"(u));
                    float rc; asm("rcp.approx.f32 %0, %1;" : "=f"(rc) : "f"(te + 1.0f));
                    float g = fmaf(-h, rc, h);                // gelu_tanh(h)
                    hh[e] = __half_as_ushort(__float2half_rn(g));
                }
                ph[e2] = hh[0] | ((uint32_t)hh[1] << 16);
            }
            uint32_t addr = (uint32_t)(m * 512) + (uint32_t)((lane ^ (m & 7)) << 4);
            *(uint4*)(smem + SMEM_A + addr) = make_uint4(ph[0], ph[1], ph[2], ph[3]);
        }
    }

    // ---- phase 2: single-pass fp16 HMMA, warp tile 32x64, 3-stage ring ----
    const int wm = wid >> 2, wn = wid & 3;
    const int M0 = wm * 32, N0 = wn * 64;
    const uint32_t s = lane & 7;
    const uint32_t ktop = lane >> 4;                       // 0/1
    const uint32_t rA = (uint32_t)M0 + ((lane >> 3) & 1) * 8 + s;
    uint32_t aBase[2];
    #pragma unroll
    for (int mf = 0; mf < 2; ++mf) aBase[mf] = sb + (rA + mf * 16) * 512;
    const uint32_t krb = ((lane >> 3) & 1) * 8 + s;        // k row within 16-row group
    uint32_t cBoff[4];
    #pragma unroll
    for (int nfp = 0; nfp < 4; ++nfp)
        cBoff[nfp] = (((uint32_t)(N0 / 8 + nfp * 2) + ktop) ^ s) << 4;

    // hoist b2 loads off the epilogue critical path
    const int colb = 2 * (lane & 3);
    float2 b2v[8];
    #pragma unroll
    for (int nf = 0; nf < 8; ++nf)
        b2v[nf] = *(const float2*)(b2 + N0 + nf * 8 + colb);

    float acc[2][8][4];
    #pragma unroll
    for (int mf = 0; mf < 2; ++mf)
        #pragma unroll
        for (int nf = 0; nf < 8; ++nf)
            #pragma unroll
            for (int e = 0; e < 4; ++e) acc[mf][nf][e] = 0.0f;

    // ring stage registers: cur = chunk c, nxt = c+1, prv = freed (gets c+2)
    uint32_t bufCur = sbB, bufNxt = sbB + 16384, bufPrv = sbB + 32768;
    const uint32_t tOff = (uint32_t)t * 16;

    #pragma unroll 1
    for (int c = 0; c < 8; ++c) {          // chunk = 32 k-rows
        if (c < 6) { CP_WAIT(1); } else { CP_WAIT(0); }
        __syncthreads();          // chunk c visible; all warps done with c-1

        // prefetch chunk c+2 into the stage chunk c-1 occupied
        if (c + 2 < 8) {
            uint32_t dst = bufPrv + tOff;
            const unsigned char* sp = gBt + (size_t)(c + 2) * 16384;
            #pragma unroll
            for (int q = 0; q < 4; ++q) cp16(dst + q * 4096, sp + q * 4096);
            CP_COMMIT();
        }

        // compute chunk c (two k16 sub-steps) from bufCur
        #pragma unroll
        for (int ks = 0; ks < 2; ++ks) {
            uint32_t ah[2][4];
            const uint32_t koffA =
                (((uint32_t)(c * 4 + ks * 2) + ktop) ^ s) << 4;
            #pragma unroll
            for (int mf = 0; mf < 2; ++mf)
                ldsm4(ah[mf], aBase[mf] + koffA);

            const uint32_t rowB = bufCur + (krb + ks * 16) * 512;
            #pragma unroll
            for (int nfp = 0; nfp < 4; ++nfp) {
                uint32_t bh[2][2];
                ldsm4t(&bh[0][0], rowB + cBoff[nfp]);
                #pragma unroll
                for (int mf = 0; mf < 2; ++mf)
                    #pragma unroll
                    for (int nn = 0; nn < 2; ++nn)
                        mma_f16(acc[mf][nfp * 2 + nn], ah[mf], bh[nn]);
            }
        }

        // rotate ring
        uint32_t tmp = bufCur;
        bufCur = bufNxt; bufNxt = bufPrv; bufPrv = tmp;
    }

    // ---- epilogue: + b2, write out [BT, 43, 256] ----
    {
        #pragma unroll
        for (int mf = 0; mf < 2; ++mf) {
            const int row = M0 + mf * 16 + (lane >> 2);
            float* p0 = out + ((size_t)(m0 + row) * NJOINT + j) * LATD;
            float* p1 = p0 + (size_t)8 * NJOINT * LATD;
            #pragma unroll
            for (int nf = 0; nf < 8; ++nf) {
                const int col = N0 + nf * 8 + colb;
                float2 v0, v1;
                v0.x = acc[mf][nf][0] + b2v[nf].x;
                v0.y = acc[mf][nf][1] + b2v[nf].y;
                v1.x = acc[mf][nf][2] + b2v[nf].x;
                v1.y = acc[mf][nf][3] + b2v[nf].y;
                *(float2*)(p0 + col) = v0;
                *(float2*)(p1 + col) = v1;
            }
        }
    }
}

extern "C" void kernel_launch(void* const* d_in, const int* in_sizes, int n_in,
                              void* d_out, int out_size)
{
    (void)in_sizes; (void)n_in; (void)out_size;
    cudaFuncSetAttribute(me_hmma_kernel,
                         cudaFuncAttributeMaxDynamicSharedMemorySize, SMEM_TOTAL);

    const float* x    = (const float*)d_in[0];
    const float* W1_3 = (const float*)d_in[1];
    const float* b1_3 = (const float*)d_in[2];
    const float* W2_3 = (const float*)d_in[3];
    const float* b2_3 = (const float*)d_in[4];
    const float* W1_2 = (const float*)d_in[5];
    const float* b1_2 = (const float*)d_in[6];
    const float* W2_2 = (const float*)d_in[7];
    const float* b2_2 = (const float*)d_in[8];
    const float* W1_1 = (const float*)d_in[9];
    const float* b1_1 = (const float*)d_in[10];
    const float* W2_1 = (const float*)d_in[11];
    const float* b2_1 = (const float*)d_in[12];

    w2_split_kernel<<<NJOINT * 8, 256>>>(W2_3, W2_2, W2_1);

    dim3 grid(BT / MT, NJOINT);   // 98 x 43
    me_hmma_kernel<<<grid, 256, SMEM_TOTAL>>>(
        x, W1_3, b1_3, b2_3,
        W1_2, b1_2, b2_2,
        W1_1, b1_1, b2_1,
        (float*)d_out);
}

// round 10
// speedup vs baseline: 1.8764x; 1.0935x over previous
#include <cuda_runtime.h>
#include <cuda_fp16.h>
#include <cstdint>

#define LATD 256
#define MT 64
#define NJOINT 43
#define BT 6272
#define XDIM 79

// main-kernel smem: A tile only
#define SMEM_TOTAL 32768    // [64 rows][512B] swizzled fp16 H

// W2 pre-packed in mma.sync B-fragment order:
// g_B[j][s=k16 step 0..15][p=n16 pair 0..15][lane 0..31] : 16B
//   16B = {b0,b1 of n8 tile at n=p*16, b0,b1 of n8 tile at n=p*16+8}
//   b0 = (B[k0][n], B[k0+1][n]), b1 = k0+8, k0 = (lane&3)*2 (+ s*16 global)
__device__ unsigned char g_B[(size_t)NJOINT * 16 * 16 * 32 * 16];   // 5.5 MB

// ---------------- helpers ----------------
__device__ __forceinline__ uint32_t smem_u32(const void* p) {
    uint32_t a;
    asm("{ .reg .u64 t; cvta.to.shared.u64 t, %1; cvt.u32.u64 %0, t; }" : "=r"(a) : "l"(p));
    return a;
}
__device__ __forceinline__ void ldsm4(uint32_t* r, uint32_t addr) {
    asm volatile("ldmatrix.sync.aligned.m8n8.x4.shared.b16 {%0,%1,%2,%3}, [%4];"
        : "=r"(r[0]), "=r"(r[1]), "=r"(r[2]), "=r"(r[3]) : "r"(addr));
}
__device__ __forceinline__ void mma_f16(float* d, const uint32_t* a, const uint32_t* b) {
    asm volatile("mma.sync.aligned.m16n8k16.row.col.f32.f16.f16.f32 "
        "{%0,%1,%2,%3}, {%4,%5,%6,%7}, {%8,%9}, {%0,%1,%2,%3};"
        : "+f"(d[0]), "+f"(d[1]), "+f"(d[2]), "+f"(d[3])
        : "r"(a[0]), "r"(a[1]), "r"(a[2]), "r"(a[3]), "r"(b[0]), "r"(b[1]));
}

// ---------------- W2 fragment-pack prologue ----------------
// grid = NJOINT*8 (j, 32-k-row chunk c); 256 threads
__global__ void __launch_bounds__(256)
w2_frag_kernel(const float* __restrict__ W2_3, const float* __restrict__ W2_2,
               const float* __restrict__ W2_1)
{
    __shared__ float ws[32 * 256];          // one k-chunk of W2, coalesced staging
    const int blk = blockIdx.x;
    const int j = blk >> 3, c = blk & 7;
    const float* W2;
    if (j < 13)      W2 = W2_3 + (size_t)j * LATD * LATD;
    else if (j < 23) W2 = W2_2 + (size_t)(j - 13) * LATD * LATD;
    else             W2 = W2_1 + (size_t)(j - 23) * LATD * LATD;

    const int t = threadIdx.x;
    const float4* src4 = (const float4*)(W2 + (size_t)c * 32 * LATD);
    float4* ws4 = (float4*)ws;
    #pragma unroll
    for (int i = 0; i < 8; ++i) ws4[t + i * 256] = src4[t + i * 256];
    __syncthreads();

    // this block covers global k16 steps s = c*2, c*2+1
    unsigned char* dst = g_B + ((size_t)j * 16 + c * 2) * (16 * 32 * 16);
    #pragma unroll
    for (int q = 0; q < 4; ++q) {
        int pid = t + q * 256;              // 0..1023
        int lane = pid & 31;
        int p    = (pid >> 5) & 15;         // n16 pair
        int ks   = pid >> 9;                // 0/1 (k16 within chunk)
        int k0 = ks * 16 + (lane & 3) * 2;  // chunk-local k
        int n  = p * 16 + (lane >> 2);
        #define PK(kk, nn) ((uint32_t)__half_as_ushort(__float2half_rn(ws[(kk) * 256 + (nn)])))
        uint4 v;
        v.x = PK(k0,     n)     | (PK(k0 + 1, n)     << 16);
        v.y = PK(k0 + 8, n)     | (PK(k0 + 9, n)     << 16);
        v.z = PK(k0,     n + 8) | (PK(k0 + 1, n + 8) << 16);
        v.w = PK(k0 + 8, n + 8) | (PK(k0 + 9, n + 8) << 16);
        #undef PK
        *(uint4*)(dst + (((size_t)ks * 16 + p) * 32 + lane) * 16) = v;
    }
}

// ---------------- main kernel ----------------
__global__ void __launch_bounds__(256, 2)
me_hmma_kernel(const float* __restrict__ x,
               const float* __restrict__ W1_3, const float* __restrict__ b1_3,
               const float* __restrict__ b2_3,
               const float* __restrict__ W1_2, const float* __restrict__ b1_2,
               const float* __restrict__ b2_2,
               const float* __restrict__ W1_1, const float* __restrict__ b1_1,
               const float* __restrict__ b2_1,
               float* __restrict__ out)
{
    extern __shared__ char smem[];
    const uint32_t sb = smem_u32(smem);
    const int t = threadIdx.x;
    const int lane = t & 31, wid = t >> 5;
    const int j = blockIdx.y;
    const int m0 = blockIdx.x * MT;

    // per-joint meta
    int d, xoff;
    const float *W1, *b1, *b2;
    if (j < 13)      { d = 3; xoff = j * 3;
        W1 = W1_3 + j * 3 * LATD; b1 = b1_3 + j * LATD; b2 = b2_3 + j * LATD; }
    else if (j < 23) { int jj = j - 13; d = 2; xoff = 39 + jj * 2;
        W1 = W1_2 + jj * 2 * LATD; b1 = b1_2 + jj * LATD; b2 = b2_2 + jj * LATD; }
    else             { int jj = j - 23; d = 1; xoff = 59 + jj;
        W1 = W1_1 + jj * LATD;     b1 = b1_1 + jj * LATD; b2 = b2_1 + jj * LATD; }

    // ---- phase 1: H = gelu_tanh(x*W1 + b1) -> swizzled fp16 A tile ----
    {
        const int kbase = lane * 8;
        float w1r[3][8], b1r[8];
        #pragma unroll
        for (int e = 0; e < 8; ++e) b1r[e] = b1[kbase + e];
        #pragma unroll
        for (int i = 0; i < 3; ++i)
            #pragma unroll
            for (int e = 0; e < 8; ++e)
                w1r[i][e] = (i < d) ? W1[i * LATD + kbase + e] : 0.0f;

        #pragma unroll 2
        for (int it = 0; it < 8; ++it) {
            const int m = wid + it * 8;
            const float* xp = x + (size_t)(m0 + m) * XDIM + xoff;
            float x0 = xp[0];
            float x1 = (d > 1) ? xp[1] : 0.0f;
            float x2 = (d > 2) ? xp[2] : 0.0f;
            uint32_t ph[4];
            #pragma unroll
            for (int e2 = 0; e2 < 4; ++e2) {
                unsigned short hh[2];
                #pragma unroll
                for (int e = 0; e < 2; ++e) {
                    const int e8 = e2 * 2 + e;
                    float h = b1r[e8] + x0 * w1r[0][e8] + x1 * w1r[1][e8] + x2 * w1r[2][e8];
                    float cc = 0.7978845608028654f * fmaf(0.044715f * h, h * h, h);
                    float u = 2.8853900817779268f * cc;       // 2c * log2(e)
                    float te; asm("ex2.approx.f32 %0, %1;" : "=f"(te) : "f"(u));
                    float rc; asm("rcp.approx.f32 %0, %1;" : "=f"(rc) : "f"(te + 1.0f));
                    float g = fmaf(-h, rc, h);                // gelu_tanh(h)
                    hh[e] = __half_as_ushort(__float2half_rn(g));
                }
                ph[e2] = hh[0] | ((uint32_t)hh[1] << 16);
            }
            uint32_t addr = (uint32_t)(m * 512) + (uint32_t)((lane ^ (m & 7)) << 4);
            *(uint4*)(smem + addr) = make_uint4(ph[0], ph[1], ph[2], ph[3]);
        }
    }
    __syncthreads();        // the ONLY barrier: A tile ready for all warps

    // ---- phase 2: fp16 HMMA, warp tile 32x64, B via direct fragment LDG ----
    const int wm = wid >> 2, wn = wid & 3;
    const int M0 = wm * 32, N0 = wn * 64;
    const uint32_t sw = lane & 7;
    const uint32_t ktop = lane >> 4;                       // 0/1
    const uint32_t rA = (uint32_t)M0 + ((lane >> 3) & 1) * 8 + sw;
    uint32_t aBase[2];
    #pragma unroll
    for (int mf = 0; mf < 2; ++mf) aBase[mf] = sb + (rA + mf * 16) * 512;

    // per-thread B fragment stream base: step s at +s*512 uint4 (8 KB)
    const uint4* gBw = (const uint4*)(g_B + (size_t)j * 16 * 8192)
                     + (wn * 4) * 32 + lane;

    float acc[2][8][4];
    #pragma unroll
    for (int mf = 0; mf < 2; ++mf)
        #pragma unroll
        for (int nf = 0; nf < 8; ++nf)
            #pragma unroll
            for (int e = 0; e < 4; ++e) acc[mf][nf][e] = 0.0f;

    uint4 bfq[2][4];          // double-buffered B frags (one k16 step each)
    #pragma unroll
    for (int nfp = 0; nfp < 4; ++nfp) bfq[0][nfp] = __ldg(gBw + nfp * 32);

    #pragma unroll
    for (int s = 0; s < 16; ++s) {
        if (s < 15) {
            const uint4* sp = gBw + (s + 1) * 512;
            #pragma unroll
            for (int nfp = 0; nfp < 4; ++nfp)
                bfq[(s + 1) & 1][nfp] = __ldg(sp + nfp * 32);
        }
        uint32_t ah[2][4];
        const uint32_t koffA = (((uint32_t)(s * 2) + ktop) ^ sw) << 4;
        #pragma unroll
        for (int mf = 0; mf < 2; ++mf)
            ldsm4(ah[mf], aBase[mf] + koffA);

        const uint32_t* b = (const uint32_t*)&bfq[s & 1][0];
        #pragma unroll
        for (int nfp = 0; nfp < 4; ++nfp)
            #pragma unroll
            for (int nn = 0; nn < 2; ++nn)
                #pragma unroll
                for (int mf = 0; mf < 2; ++mf)
                    mma_f16(acc[mf][nfp * 2 + nn], ah[mf], b + nfp * 4 + nn * 2);
    }

    // ---- epilogue: + b2, write out [BT, 43, 256] ----
    {
        const int colb = 2 * (lane & 3);
        float2 b2v[8];
        #pragma unroll
        for (int nf = 0; nf < 8; ++nf)
            b2v[nf] = *(const float2*)(b2 + N0 + nf * 8 + colb);
        #pragma unroll
        for (int mf = 0; mf < 2; ++mf) {
            const int row = M0 + mf * 16 + (lane >> 2);
            float* p0 = out + ((size_t)(m0 + row) * NJOINT + j) * LATD;
            float* p1 = p0 + (size_t)8 * NJOINT * LATD;
            #pragma unroll
            for (int nf = 0; nf < 8; ++nf) {
                const int col = N0 + nf * 8 + colb;
                float2 v0, v1;
                v0.x = acc[mf][nf][0] + b2v[nf].x;
                v0.y = acc[mf][nf][1] + b2v[nf].y;
                v1.x = acc[mf][nf][2] + b2v[nf].x;
                v1.y = acc[mf][nf][3] + b2v[nf].y;
                *(float2*)(p0 + col) = v0;
                *(float2*)(p1 + col) = v1;
            }
        }
    }
}

extern "C" void kernel_launch(void* const* d_in, const int* in_sizes, int n_in,
                              void* d_out, int out_size)
{
    (void)in_sizes; (void)n_in; (void)out_size;
    cudaFuncSetAttribute(me_hmma_kernel,
                         cudaFuncAttributeMaxDynamicSharedMemorySize, SMEM_TOTAL);

    const float* x    = (const float*)d_in[0];
    const float* W1_3 = (const float*)d_in[1];
    const float* b1_3 = (const float*)d_in[2];
    const float* W2_3 = (const float*)d_in[3];
    const float* b2_3 = (const float*)d_in[4];
    const float* W1_2 = (const float*)d_in[5];
    const float* b1_2 = (const float*)d_in[6];
    const float* W2_2 = (const float*)d_in[7];
    const float* b2_2 = (const float*)d_in[8];
    const float* W1_1 = (const float*)d_in[9];
    const float* b1_1 = (const float*)d_in[10];
    const float* W2_1 = (const float*)d_in[11];
    const float* b2_1 = (const float*)d_in[12];

    w2_frag_kernel<<<NJOINT * 8, 256>>>(W2_3, W2_2, W2_1);

    dim3 grid(BT / MT, NJOINT);   // 98 x 43
    me_hmma_kernel<<<grid, 256, SMEM_TOTAL>>>(
        x, W1_3, b1_3, b2_3,
        W1_2, b1_2, b2_2,
        W1_1, b1_1, b2_1,
        (float*)d_out);
}